// round 2
// baseline (speedup 1.0000x reference)
#include <cuda_runtime.h>

typedef unsigned long long u64;

#define NLAY    3
#define TSTEPS  128
#define MTILE   128
#define NTHREADS 512

// Pre-transposed weights (filled by prep_kernel every launch):
//   g_embT[k*64 + c]            = emb_w[c*64 + k]
//   g_wT[(l*64 + k)*384 + c]    = (c<192) ? w_ih[l][c][k] : w_hh[l][c-192][k]
__device__ __align__(16) float g_embT[64 * 64];
__device__ __align__(16) float g_wT[NLAY * 64 * 384];

__global__ void prep_kernel(const float* __restrict__ emb_w,
                            const float* __restrict__ w_ih,
                            const float* __restrict__ w_hh)
{
    int t0 = blockIdx.x * blockDim.x + threadIdx.x;
    int stride = gridDim.x * blockDim.x;
    for (int i = t0; i < 64 * 64; i += stride) {
        int c = i >> 6, k = i & 63;          // i = c*64 + k
        g_embT[k * 64 + c] = emb_w[i];
    }
    for (int i = t0; i < NLAY * 64 * 384; i += stride) {
        int l = i / (64 * 384);
        int rem = i - l * (64 * 384);
        int k = rem / 384;
        int c = rem - k * 384;
        g_wT[i] = (c < 192) ? w_ih[(l * 192 + c) * 64 + k]
                            : w_hh[(l * 192 + (c - 192)) * 64 + k];
    }
}

// ---- packed f32x2 helpers ----
__device__ __forceinline__ u64 dup2(float v) {
    u64 d; asm("mov.b64 %0,{%1,%1};" : "=l"(d) : "f"(v)); return d;
}
__device__ __forceinline__ u64 pk2(float a, float b) {
    u64 d; asm("mov.b64 %0,{%1,%2};" : "=l"(d) : "f"(a), "f"(b)); return d;
}
__device__ __forceinline__ void up2(u64 v, float& a, float& b) {
    asm("mov.b64 {%0,%1},%2;" : "=f"(a), "=f"(b) : "l"(v));
}
__device__ __forceinline__ u64 f2fma(u64 a, u64 b, u64 c) {
    u64 d; asm("fma.rn.f32x2 %0,%1,%2,%3;" : "=l"(d) : "l"(a), "l"(b), "l"(c));
    return d;
}
__device__ __forceinline__ void ldg2(const float* p, u64& a, u64& b) {
    asm("ld.global.nc.v2.b64 {%0,%1},[%2];" : "=l"(a), "=l"(b) : "l"(p));
}
__device__ __forceinline__ float sigmf(float x) {
    return __fdividef(1.f, 1.f + __expf(-x));
}
__device__ __forceinline__ float tanhfast(float x) {
    return 1.f - __fdividef(2.f, __expf(2.f * x) + 1.f);
}

// Persistent per-CTA GRU decoder: 128 rows/CTA, all 128 steps.
// SMEM: sX, sH0, sH1, sH2 each [64 feat][128 rows] (feature-major).
extern "C" __global__ void __launch_bounds__(NTHREADS, 1)
gru_kernel(const float* __restrict__ enc,
           const float* __restrict__ emb_b,
           const float* __restrict__ b_ih,
           const float* __restrict__ b_hh,
           const float* __restrict__ out_w,
           const float* __restrict__ out_b,
           float* __restrict__ out)
{
    extern __shared__ float sm[];      // 4 * 8192 floats = 128 KB
    const int tid  = threadIdx.x;
    const int row0 = blockIdx.x * MTILE;
    const int c0 = (tid & 15) * 4;     // 16 col groups x 4 cols = 64
    const int r0 = (tid >> 4) * 4;     // 32 row groups x 4 rows = 128

    // init all three hidden states to enc (transposed)
    for (int i = tid; i < 64 * MTILE; i += NTHREADS) {
        int m = i >> 6, e = i & 63;                 // coalesced enc read
        float v = enc[(size_t)(row0 + m) * 64 + e];
        sm[8192  + e * 128 + m] = v;
        sm[16384 + e * 128 + m] = v;
        sm[24576 + e * 128 + m] = v;
    }
    __syncthreads();

    // embedding bias (constant over t)
    const float4 ebv = *(const float4*)(emb_b + c0);
    const u64 embB0 = pk2(ebv.x, ebv.y);
    const u64 embB1 = pk2(ebv.z, ebv.w);
    const int om = tid & 127;          // output-layer mapping (tid<256)
    const int oj = tid >> 7;

    for (int t = 0; t < TSTEPS; t++) {
        float* sH2 = sm + 24576;

        // ========= embedding: sX = sH2 @ emb_w^T + emb_b =========
        {
            u64 a0[4], a1[4];
            #pragma unroll
            for (int r = 0; r < 4; r++) { a0[r] = embB0; a1[r] = embB1; }
            #pragma unroll 4
            for (int k = 0; k < 64; k++) {
                float4 x4 = *(const float4*)(sH2 + k * 128 + r0);
                u64 w0, w1; ldg2(g_embT + k * 64 + c0, w0, w1);
                float xs[4] = {x4.x, x4.y, x4.z, x4.w};
                #pragma unroll
                for (int r = 0; r < 4; r++) {
                    u64 xd = dup2(xs[r]);
                    a0[r] = f2fma(xd, w0, a0[r]);
                    a1[r] = f2fma(xd, w1, a1[r]);
                }
            }
            float v[4][4];
            #pragma unroll
            for (int r = 0; r < 4; r++) {
                up2(a0[r], v[r][0], v[r][1]);
                up2(a1[r], v[r][2], v[r][3]);
            }
            #pragma unroll
            for (int cc = 0; cc < 4; cc++)
                *(float4*)(sm + (c0 + cc) * 128 + r0) =
                    make_float4(v[0][cc], v[1][cc], v[2][cc], v[3][cc]);
        }
        __syncthreads();

        // ========= 3 GRU layers =========
        #pragma unroll 1
        for (int l = 0; l < NLAY; l++) {
            const float* Xb = sm + l * 8192;        // l=0 -> sX
            float*       Hb = sm + (l + 1) * 8192;  // sH_l

            u64 aR[4][2], aZ[4][2], aN[4][2], aM[4][2];
            {
                const float* bi = b_ih + l * 192 + c0;
                const float* bh = b_hh + l * 192 + c0;
                float4 bir = *(const float4*)bi,        bhr = *(const float4*)bh;
                float4 biz = *(const float4*)(bi + 64), bhz = *(const float4*)(bh + 64);
                float4 bin = *(const float4*)(bi + 128), bhn = *(const float4*)(bh + 128);
                u64 iR0 = pk2(bir.x + bhr.x, bir.y + bhr.y), iR1 = pk2(bir.z + bhr.z, bir.w + bhr.w);
                u64 iZ0 = pk2(biz.x + bhz.x, biz.y + bhz.y), iZ1 = pk2(biz.z + bhz.z, biz.w + bhz.w);
                u64 iN0 = pk2(bin.x, bin.y), iN1 = pk2(bin.z, bin.w);
                u64 iM0 = pk2(bhn.x, bhn.y), iM1 = pk2(bhn.z, bhn.w);
                #pragma unroll
                for (int r = 0; r < 4; r++) {
                    aR[r][0] = iR0; aR[r][1] = iR1;
                    aZ[r][0] = iZ0; aZ[r][1] = iZ1;
                    aN[r][0] = iN0; aN[r][1] = iN1;
                    aM[r][0] = iM0; aM[r][1] = iM1;
                }
            }

            const float* wbase = g_wT + (l * 64) * 384 + c0;
            #pragma unroll 2
            for (int k = 0; k < 64; k++) {
                float4 x4 = *(const float4*)(Xb + k * 128 + r0);
                float4 h4 = *(const float4*)(Hb + k * 128 + r0);
                const float* wr = wbase + k * 384;
                u64 wir0, wir1, wiz0, wiz1, win0, win1;
                u64 whr0, whr1, whz0, whz1, whn0, whn1;
                ldg2(wr,       wir0, wir1);
                ldg2(wr + 64,  wiz0, wiz1);
                ldg2(wr + 128, win0, win1);
                ldg2(wr + 192, whr0, whr1);
                ldg2(wr + 256, whz0, whz1);
                ldg2(wr + 320, whn0, whn1);
                float xs[4] = {x4.x, x4.y, x4.z, x4.w};
                float hs[4] = {h4.x, h4.y, h4.z, h4.w};
                #pragma unroll
                for (int r = 0; r < 4; r++) {
                    u64 xd = dup2(xs[r]), hd = dup2(hs[r]);
                    aR[r][0] = f2fma(xd, wir0, aR[r][0]);
                    aR[r][0] = f2fma(hd, whr0, aR[r][0]);
                    aR[r][1] = f2fma(xd, wir1, aR[r][1]);
                    aR[r][1] = f2fma(hd, whr1, aR[r][1]);
                    aZ[r][0] = f2fma(xd, wiz0, aZ[r][0]);
                    aZ[r][0] = f2fma(hd, whz0, aZ[r][0]);
                    aZ[r][1] = f2fma(xd, wiz1, aZ[r][1]);
                    aZ[r][1] = f2fma(hd, whz1, aZ[r][1]);
                    aN[r][0] = f2fma(xd, win0, aN[r][0]);
                    aN[r][1] = f2fma(xd, win1, aN[r][1]);
                    aM[r][0] = f2fma(hd, whn0, aM[r][0]);
                    aM[r][1] = f2fma(hd, whn1, aM[r][1]);
                }
            }
            __syncthreads();   // all reads of Hb done before overwrite

            #pragma unroll
            for (int cc = 0; cc < 4; cc++) {
                float4 ho = *(const float4*)(Hb + (c0 + cc) * 128 + r0);
                float hos[4] = {ho.x, ho.y, ho.z, ho.w};
                float res[4];
                #pragma unroll
                for (int r = 0; r < 4; r++) {
                    float p0, p1, R, Z, N, M;
                    up2(aR[r][cc >> 1], p0, p1); R = (cc & 1) ? p1 : p0;
                    up2(aZ[r][cc >> 1], p0, p1); Z = (cc & 1) ? p1 : p0;
                    up2(aN[r][cc >> 1], p0, p1); N = (cc & 1) ? p1 : p0;
                    up2(aM[r][cc >> 1], p0, p1); M = (cc & 1) ? p1 : p0;
                    float rg = sigmf(R);
                    float zg = sigmf(Z);
                    float ng = tanhfast(fmaf(rg, M, N));
                    res[r] = fmaf(zg, hos[r] - ng, ng);
                }
                *(float4*)(Hb + (c0 + cc) * 128 + r0) =
                    make_float4(res[0], res[1], res[2], res[3]);
            }
            __syncthreads();
        }

        // ========= output: out[:, t, :] = sH2 @ out_w^T + out_b =========
        if (tid < 256) {
            float a = out_b[oj];
            const float* ow = out_w + oj * 64;
            #pragma unroll 8
            for (int e = 0; e < 64; e++)
                a = fmaf(sH2[e * 128 + om], ow[e], a);
            out[(size_t)(row0 + om) * (TSTEPS * 2) + t * 2 + oj] = a;
        }
        // no sync needed: next emb only READS sH2 (as does the output pass)
    }
}

extern "C" void kernel_launch(void* const* d_in, const int* in_sizes, int n_in,
                              void* d_out, int out_size)
{
    const float* enc   = (const float*)d_in[0];
    const float* emb_w = (const float*)d_in[1];
    const float* emb_b = (const float*)d_in[2];
    const float* w_ih  = (const float*)d_in[3];
    const float* w_hh  = (const float*)d_in[4];
    const float* b_ih  = (const float*)d_in[5];
    const float* b_hh  = (const float*)d_in[6];
    const float* out_w = (const float*)d_in[7];
    const float* out_b = (const float*)d_in[8];

    cudaFuncSetAttribute(gru_kernel,
                         cudaFuncAttributeMaxDynamicSharedMemorySize,
                         131072);

    prep_kernel<<<64, 256>>>(emb_w, w_ih, w_hh);
    gru_kernel<<<128, NTHREADS, 131072>>>(enc, emb_b, b_ih, b_hh,
                                          out_w, out_b, (float*)d_out);
}